// round 2
// baseline (speedup 1.0000x reference)
#include <cuda_runtime.h>
#include <math.h>

#define BATCH 32
#define NTOK 1024
#define CDIM 1024
#define NHEADS 16
#define HD 64
#define AGENTS 49
#define NTHREADS 256

// Precomputed effective rank-3 weights and biases
__device__ float g_Wq[3 * CDIM];
__device__ float g_Wk[3 * CDIM];
__device__ float g_Wv[3 * CDIM];
__device__ float g_bq[CDIM];
__device__ float g_bk[CDIM];
__device__ float g_bv[CDIM];
// Scratch: (O + V_dwc) as [B, N, C]
__device__ float g_scratch[(size_t)BATCH * NTOK * CDIM];

__device__ __forceinline__ float warp_max(float v) {
    #pragma unroll
    for (int o = 16; o; o >>= 1) v = fmaxf(v, __shfl_xor_sync(0xffffffffu, v, o));
    return v;
}
__device__ __forceinline__ float warp_sum(float v) {
    #pragma unroll
    for (int o = 16; o; o >>= 1) v += __shfl_xor_sync(0xffffffffu, v, o);
    return v;
}

// ---------------------------------------------------------------------------
// Kernel 0: fold the 3->1024 embed with the 1024->1024 projections.
// W_q = w_vel @ wq (3x1024);  b_q = b_vel @ wq + bq;  similarly K,V via w_init.
// ---------------------------------------------------------------------------
__global__ void prep_kernel(const float* __restrict__ w_vel, const float* __restrict__ b_vel,
                            const float* __restrict__ w_init, const float* __restrict__ b_init,
                            const float* __restrict__ wq, const float* __restrict__ bq,
                            const float* __restrict__ wk, const float* __restrict__ bk,
                            const float* __restrict__ wv, const float* __restrict__ bv) {
    int gid = blockIdx.x * blockDim.x + threadIdx.x;
    if (gid < 9 * CDIM) {
        int mat = gid / (3 * CDIM);
        int rem = gid % (3 * CDIM);
        int i = rem / CDIM, c = rem % CDIM;
        const float* A = (mat == 0) ? w_vel : w_init;
        const float* W = (mat == 0) ? wq : (mat == 1 ? wk : wv);
        float* O = (mat == 0) ? g_Wq : (mat == 1 ? g_Wk : g_Wv);
        float s = 0.f;
        for (int j = 0; j < CDIM; j++) s = fmaf(A[i * CDIM + j], W[j * CDIM + c], s);
        O[i * CDIM + c] = s;
    } else if (gid < 12 * CDIM) {
        int rem = gid - 9 * CDIM;
        int mat = rem / CDIM, c = rem % CDIM;
        const float* bvec = (mat == 0) ? b_vel : b_init;
        const float* W = (mat == 0) ? wq : (mat == 1 ? wk : wv);
        const float* badd = (mat == 0) ? bq : (mat == 1 ? bk : bv);
        float* O = (mat == 0) ? g_bq : (mat == 1 ? g_bk : g_bv);
        float s = badd[c];
        for (int j = 0; j < CDIM; j++) s = fmaf(bvec[j], W[j * CDIM + c], s);
        O[c] = s;
    }
}

// ---------------------------------------------------------------------------
// Kernel 1: fused agent attention per (batch, head). One CTA per (b,h).
// Writes (O + V_dwc) to g_scratch[b, n, h*64+d].
// ---------------------------------------------------------------------------
__global__ __launch_bounds__(NTHREADS) void agent_kernel(
    const float* __restrict__ Qg_all, const float* __restrict__ Kg_all,
    const float* __restrict__ Vg_all,
    const float* __restrict__ bias1,   // [49, 1024]
    const float* __restrict__ bias2,   // [1024, 49]
    const float* __restrict__ dwc_w,   // [1024, 1, 3, 3]
    const float* __restrict__ dwc_b)   // [1024]
{
    __shared__ float sK[NTOK * 3];       // 3072
    __shared__ float sV[NTOK * 3];       // 3072
    __shared__ float sAg[AGENTS * HD];   // 3136: agent, later agent_values
    __shared__ float sCK[AGENTS * 4];
    __shared__ float sCQ[AGENTS * 4];
    __shared__ float sPool[AGENTS * 4];  // pooled Q [a][3]
    __shared__ float sRow[AGENTS * 4];   // normalized pv [a][3]
    __shared__ float sWq[3 * HD], sWk[3 * HD], sWv[3 * HD];
    __shared__ float sbq[HD], sbk[HD], sbv[HD];
    __shared__ float sDw[4 * HD];        // tap0, tap1, tap2, bias

    const int tid = threadIdx.x;
    const int h = blockIdx.x;
    const int b = blockIdx.y;
    const float* Qg = Qg_all + (size_t)b * NTOK * 3;
    const float* Kg = Kg_all + (size_t)b * NTOK * 3;
    const float* Vg = Vg_all + (size_t)b * NTOK * 3;

    // ---- Stage A: load K, V rows and per-head weight slices ----
    for (int idx = tid; idx < NTOK * 3; idx += NTHREADS) {
        sK[idx] = Kg[idx];
        sV[idx] = Vg[idx];
    }
    for (int idx = tid; idx < 3 * HD; idx += NTHREADS) {
        int i = idx / HD, d = idx % HD;
        int c = h * HD + d;
        sWq[idx] = g_Wq[i * CDIM + c];
        sWk[idx] = g_Wk[i * CDIM + c];
        sWv[idx] = g_Wv[i * CDIM + c];
    }
    if (tid < HD) {
        int c = h * HD + tid;
        sbq[tid] = g_bq[c];
        sbk[tid] = g_bk[c];
        sbv[tid] = g_bv[c];
        sDw[tid]          = dwc_w[c * 9 + 1];  // kh=0, kw=1
        sDw[HD + tid]     = dwc_w[c * 9 + 4];  // kh=1, kw=1
        sDw[2 * HD + tid] = dwc_w[c * 9 + 7];  // kh=2, kw=1
        sDw[3 * HD + tid] = dwc_b[c];
    }
    __syncthreads();

    // ---- Stage B: adaptive avg pool of raw Q -> pooledQ[a][3] ----
    for (int idx = tid; idx < AGENTS * 3; idx += NTHREADS) {
        int a = idx / 3, i = idx % 3;
        int s = (a * NTOK) / AGENTS;
        int e = ((a + 1) * NTOK + AGENTS - 1) / AGENTS;
        float acc = 0.f;
        for (int n = s; n < e; n++) acc += Qg[n * 3 + i];
        sPool[a * 4 + i] = acc / (float)(e - s);
    }
    __syncthreads();

    // ---- Stage C: agent[a][d] = pooledQ[a]·Wq[:,d] + bq[d] ----
    for (int idx = tid; idx < AGENTS * HD; idx += NTHREADS) {
        int a = idx / HD, d = idx % HD;
        float v = sbq[d];
        v = fmaf(sPool[a * 4 + 0], sWq[d], v);
        v = fmaf(sPool[a * 4 + 1], sWq[HD + d], v);
        v = fmaf(sPool[a * 4 + 2], sWq[2 * HD + d], v);
        sAg[idx] = v;
    }
    __syncthreads();

    // ---- Stage D: ck[a][0..3] = agent[a]·{Wk rows, bk};  cq likewise ----
    for (int idx = tid; idx < AGENTS * 8; idx += NTHREADS) {
        int a = idx / 8, j = idx % 8;
        const float* ag = &sAg[a * HD];
        if (j < 4) {
            const float* w = (j < 3) ? &sWk[j * HD] : sbk;
            float v = 0.f;
            #pragma unroll 8
            for (int d = 0; d < HD; d++) v = fmaf(ag[d], w[d], v);
            sCK[a * 4 + j] = v;
        } else {
            int j2 = j - 4;
            const float* w = (j2 < 3) ? &sWq[j2 * HD] : sbq;
            float v = 0.f;
            #pragma unroll 8
            for (int d = 0; d < HD; d++) v = fmaf(ag[d], w[d], v);
            sCQ[a * 4 + j2] = v;
        }
    }
    __syncthreads();

    // ---- Stage E: stage-1 softmax over n (length 1024) per agent row a.
    //      Scores S1[a,n] = ck·K[n] + ck3 + bias1[a,n].  One warp per row.
    //      Only the softmax-weighted 3-vector of V (pv) is needed.
    {
        const int warp = tid >> 5;
        const int lane = tid & 31;
        for (int a = warp; a < AGENTS; a += NTHREADS / 32) {
            const float ck0 = sCK[a * 4 + 0], ck1 = sCK[a * 4 + 1];
            const float ck2 = sCK[a * 4 + 2], ck3 = sCK[a * 4 + 3];
            const float* b1 = bias1 + a * NTOK;
            float p[32];
            float m = -1e30f;
            #pragma unroll
            for (int j = 0; j < 32; j++) {
                int n = j * 32 + lane;
                float v = ck3 + b1[n];
                v = fmaf(ck0, sK[n * 3 + 0], v);
                v = fmaf(ck1, sK[n * 3 + 1], v);
                v = fmaf(ck2, sK[n * 3 + 2], v);
                p[j] = v;
                m = fmaxf(m, v);
            }
            m = warp_max(m);
            float sum = 0.f, pv0 = 0.f, pv1 = 0.f, pv2 = 0.f;
            #pragma unroll
            for (int j = 0; j < 32; j++) {
                int n = j * 32 + lane;
                float e = __expf(p[j] - m);
                sum += e;
                pv0 = fmaf(e, sV[n * 3 + 0], pv0);
                pv1 = fmaf(e, sV[n * 3 + 1], pv1);
                pv2 = fmaf(e, sV[n * 3 + 2], pv2);
            }
            sum = warp_sum(sum);
            pv0 = warp_sum(pv0);
            pv1 = warp_sum(pv1);
            pv2 = warp_sum(pv2);
            if (lane == 0) {
                float inv = 1.f / sum;
                sRow[a * 4 + 0] = pv0 * inv;
                sRow[a * 4 + 1] = pv1 * inv;
                sRow[a * 4 + 2] = pv2 * inv;
            }
        }
    }
    __syncthreads();

    // ---- Stage F: agent_values[a][d] = pv[a]·Wv[:,d] + bv[d] (overwrite sAg) ----
    for (int idx = tid; idx < AGENTS * HD; idx += NTHREADS) {
        int a = idx / HD, d = idx % HD;
        float v = sbv[d];
        v = fmaf(sRow[a * 4 + 0], sWv[d], v);
        v = fmaf(sRow[a * 4 + 1], sWv[HD + d], v);
        v = fmaf(sRow[a * 4 + 2], sWv[2 * HD + d], v);
        sAg[idx] = v;
    }
    __syncthreads();

    // ---- Stage G: per-token stage-2 softmax over 49 agents, O = p2 @ AV,
    //      plus fused depthwise 3-tap conv residual, write scratch. ----
    for (int r = 0; r < NTOK / NTHREADS; r++) {
        int n = tid + r * NTHREADS;
        float q0 = Qg[n * 3 + 0], q1 = Qg[n * 3 + 1], q2 = Qg[n * 3 + 2];
        const float* b2 = bias2 + n * AGENTS;

        float s2[AGENTS];
        float m = -1e30f;
        #pragma unroll
        for (int a = 0; a < AGENTS; a++) {
            float v = sCQ[a * 4 + 3] + b2[a];
            v = fmaf(sCQ[a * 4 + 0], q0, v);
            v = fmaf(sCQ[a * 4 + 1], q1, v);
            v = fmaf(sCQ[a * 4 + 2], q2, v);
            s2[a] = v;
            m = fmaxf(m, v);
        }
        float sum = 0.f;
        #pragma unroll
        for (int a = 0; a < AGENTS; a++) {
            float e = __expf(s2[a] - m);
            s2[a] = e;
            sum += e;
        }
        float inv = 1.f / sum;

        // V rows for the 3-tap conv (zero-padded at edges)
        float vc0 = sV[n * 3 + 0], vc1 = sV[n * 3 + 1], vc2 = sV[n * 3 + 2];
        bool hm = (n > 0), hp = (n < NTOK - 1);
        float vm0 = hm ? sV[(n - 1) * 3 + 0] : 0.f;
        float vm1 = hm ? sV[(n - 1) * 3 + 1] : 0.f;
        float vm2 = hm ? sV[(n - 1) * 3 + 2] : 0.f;
        float vp0 = hp ? sV[(n + 1) * 3 + 0] : 0.f;
        float vp1 = hp ? sV[(n + 1) * 3 + 1] : 0.f;
        float vp2 = hp ? sV[(n + 1) * 3 + 2] : 0.f;

        float* dst = g_scratch + ((size_t)(b * NTOK + n) * CDIM) + h * HD;
        #pragma unroll 4
        for (int d = 0; d < HD; d++) {
            float o = 0.f;
            #pragma unroll
            for (int a = 0; a < AGENTS; a++) o = fmaf(s2[a], sAg[a * HD + d], o);
            o *= inv;

            float wv0 = sWv[d], wv1 = sWv[HD + d], wv2 = sWv[2 * HD + d];
            float bvd = sbv[d];
            float vh0 = fmaf(vc0, wv0, fmaf(vc1, wv1, fmaf(vc2, wv2, bvd)));
            float vhm = hm ? fmaf(vm0, wv0, fmaf(vm1, wv1, fmaf(vm2, wv2, bvd))) : 0.f;
            float vhp = hp ? fmaf(vp0, wv0, fmaf(vp1, wv1, fmaf(vp2, wv2, bvd))) : 0.f;
            float vd = sDw[3 * HD + d];
            vd = fmaf(vhm, sDw[d], vd);
            vd = fmaf(vh0, sDw[HD + d], vd);
            vd = fmaf(vhp, sDw[2 * HD + d], vd);

            dst[d] = o + vd;
        }
    }
}

// ---------------------------------------------------------------------------
// Kernel 2: out[b, j, n] = scratch[b, n, :] · w_proj[:, j] + b_proj[j].
// One warp per (b, n) row; lanes stride over c (coalesced).
// ---------------------------------------------------------------------------
__global__ __launch_bounds__(NTHREADS) void proj_kernel(
    const float* __restrict__ w_proj,  // [1024, 3]
    const float* __restrict__ b_proj,  // [3]
    float* __restrict__ out)           // [B, 3, N]
{
    int gw = (blockIdx.x * NTHREADS + threadIdx.x) >> 5;
    int lane = threadIdx.x & 31;
    int b = gw >> 10;
    int n = gw & 1023;
    const float* row = g_scratch + ((size_t)(b * NTOK + n) * CDIM);
    float a0 = 0.f, a1 = 0.f, a2 = 0.f;
    #pragma unroll 4
    for (int c = lane; c < CDIM; c += 32) {
        float s = row[c];
        a0 = fmaf(s, w_proj[c * 3 + 0], a0);
        a1 = fmaf(s, w_proj[c * 3 + 1], a1);
        a2 = fmaf(s, w_proj[c * 3 + 2], a2);
    }
    a0 = warp_sum(a0);
    a1 = warp_sum(a1);
    a2 = warp_sum(a2);
    if (lane == 0) {
        out[b * 3 * NTOK + n]            = a0 + b_proj[0];
        out[b * 3 * NTOK + NTOK + n]     = a1 + b_proj[1];
        out[b * 3 * NTOK + 2 * NTOK + n] = a2 + b_proj[2];
    }
}

extern "C" void kernel_launch(void* const* d_in, const int* in_sizes, int n_in,
                              void* d_out, int out_size) {
    const float* Q      = (const float*)d_in[0];
    const float* K      = (const float*)d_in[1];
    const float* V      = (const float*)d_in[2];
    const float* w_vel  = (const float*)d_in[3];
    const float* b_vel  = (const float*)d_in[4];
    const float* w_init = (const float*)d_in[5];
    const float* b_init = (const float*)d_in[6];
    const float* wq     = (const float*)d_in[7];
    const float* bq     = (const float*)d_in[8];
    const float* wk     = (const float*)d_in[9];
    const float* bk     = (const float*)d_in[10];
    const float* wv     = (const float*)d_in[11];
    const float* bv     = (const float*)d_in[12];
    const float* ab1    = (const float*)d_in[13];
    const float* ab2    = (const float*)d_in[14];
    const float* dwc_w  = (const float*)d_in[15];
    const float* dwc_b  = (const float*)d_in[16];
    const float* w_proj = (const float*)d_in[17];
    const float* b_proj = (const float*)d_in[18];
    float* out = (float*)d_out;

    prep_kernel<<<48, NTHREADS>>>(w_vel, b_vel, w_init, b_init,
                                  wq, bq, wk, bk, wv, bv);
    agent_kernel<<<dim3(NHEADS, BATCH), NTHREADS>>>(Q, K, V, ab1, ab2, dwc_w, dwc_b);
    proj_kernel<<<(BATCH * NTOK * 32) / NTHREADS, NTHREADS>>>(w_proj, b_proj, out);
}

// round 3
// speedup vs baseline: 7.4566x; 7.4566x over previous
#include <cuda_runtime.h>
#include <math.h>

#define BATCH 32
#define NTOK 1024
#define CDIM 1024
#define NHEADS 16
#define HD 64
#define AGENTS 49

// ---------------- precomputed small tensors ----------------
__device__ float g_part[3 * 8 * 4 * 1024];     // j-split partials for weight fold
__device__ float g_W[12][CDIM];                // [mat*4+row]: rows 0-2 weight, 3 bias; mat 0=Q,1=K,2=V
__device__ float g_CkM[NHEADS][4][4];          // stage-1 score coeff matrix per head
__device__ float g_CqM[NHEADS][4][4];          // stage-2 score coeff matrix per head
__device__ float g_G[NHEADS][3][3];            // Wv_h @ w_proj_h
__device__ float g_Et[3][3][3];                // dwc tap x rank-i x out-j
__device__ float g_Ebt[3][3];                  // dwc tap bias terms
__device__ float g_Const[3];                   // constant per output channel
__device__ float g_b2T[AGENTS * NTOK];         // bias2 transposed [a][n]
__device__ float g_pool[BATCH][AGENTS][3];     // pooled raw Q
__device__ float4 g_cq[BATCH * NHEADS * AGENTS];
__device__ float4 g_pv[BATCH * NHEADS * AGENTS];

__device__ __forceinline__ float warp_max(float v) {
    #pragma unroll
    for (int o = 16; o; o >>= 1) v = fmaxf(v, __shfl_xor_sync(0xffffffffu, v, o));
    return v;
}
__device__ __forceinline__ float warp_sum(float v) {
    #pragma unroll
    for (int o = 16; o; o >>= 1) v += __shfl_xor_sync(0xffffffffu, v, o);
    return v;
}

// ---------------------------------------------------------------------------
// prepA: partial fold of [w_vel|b_vel] @ wq etc, split 8x along j for occupancy
// ---------------------------------------------------------------------------
__global__ void prepA(const float* __restrict__ w_vel, const float* __restrict__ b_vel,
                      const float* __restrict__ w_init, const float* __restrict__ b_init,
                      const float* __restrict__ wq, const float* __restrict__ wk,
                      const float* __restrict__ wv) {
    int mat = blockIdx.z, jz = blockIdx.y;
    int c = blockIdx.x * 256 + threadIdx.x;
    const float* W = (mat == 0) ? wq : (mat == 1 ? wk : wv);
    const float* A = (mat == 0) ? w_vel : w_init;
    const float* bb = (mat == 0) ? b_vel : b_init;
    float a0 = 0.f, a1 = 0.f, a2 = 0.f, a3 = 0.f;
    int j0 = jz * 128;
    #pragma unroll 4
    for (int j = j0; j < j0 + 128; j++) {
        float w = W[j * CDIM + c];
        a0 = fmaf(__ldg(A + j), w, a0);
        a1 = fmaf(__ldg(A + CDIM + j), w, a1);
        a2 = fmaf(__ldg(A + 2 * CDIM + j), w, a2);
        a3 = fmaf(__ldg(bb + j), w, a3);
    }
    float* p = g_part + ((mat * 8 + jz) * 4) * CDIM + c;
    p[0] = a0; p[CDIM] = a1; p[2 * CDIM] = a2; p[3 * CDIM] = a3;
}

// prepB: reduce the 8 j-splits, add trailing bias for row 3
__global__ void prepB(const float* __restrict__ bq, const float* __restrict__ bk,
                      const float* __restrict__ bv) {
    int gid = blockIdx.x * 256 + threadIdx.x;   // 12*1024
    int mat = gid >> 12;
    int r = (gid >> 10) & 3;
    int c = gid & 1023;
    float s = 0.f;
    #pragma unroll
    for (int jz = 0; jz < 8; jz++)
        s += g_part[((mat * 8 + jz) * 4 + r) * CDIM + c];
    if (r == 3) s += (mat == 0 ? bq : (mat == 1 ? bk : bv))[c];
    g_W[mat * 4 + r][c] = s;
}

// ---------------------------------------------------------------------------
// prepC: per-head coefficient matrices + projection-folded tensors
// blocks 0..15: head h -> CkM, CqM, G.   blocks 16..20: Et/Ebt/Const (warp/dot)
// ---------------------------------------------------------------------------
__global__ void prepC(const float* __restrict__ w_proj, const float* __restrict__ b_proj,
                      const float* __restrict__ dwc_w, const float* __restrict__ dwc_b) {
    int tid = threadIdx.x;
    if (blockIdx.x < 16) {
        int h = blockIdx.x;
        if (tid < 41) {
            if (tid < 32) {
                int q = tid & 15;
                int j = q >> 2, i = q & 3;
                const float* rq = &g_W[0 + ((j < 3) ? j : 3)][h * HD];
                const float* rx = (tid < 16) ? &g_W[4 + ((i < 3) ? i : 3)][h * HD]
                                             : &g_W[0 + ((i < 3) ? i : 3)][h * HD];
                float s = 0.f;
                #pragma unroll 8
                for (int d = 0; d < HD; d++) s = fmaf(rq[d], rx[d], s);
                if (tid < 16) g_CkM[h][j][i] = s; else g_CqM[h][j][i] = s;
            } else {
                int kk = tid - 32;
                int i = kk / 3, j = kk % 3;
                const float* rv = &g_W[8 + i][h * HD];
                float s = 0.f;
                #pragma unroll 8
                for (int d = 0; d < HD; d++)
                    s = fmaf(rv[d], w_proj[(h * HD + d) * 3 + j], s);
                g_G[h][i][j] = s;
            }
        }
    } else {
        int wg = (blockIdx.x - 16) * 8 + (tid >> 5);
        int lane = tid & 31;
        float acc = 0.f;
        if (wg < 27) {
            int t = wg / 9, rem = wg % 9, i = rem / 3, j = rem % 3;
            for (int c = lane; c < CDIM; c += 32)
                acc = fmaf(dwc_w[c * 9 + t * 3 + 1] * g_W[8 + i][c], w_proj[c * 3 + j], acc);
            acc = warp_sum(acc);
            if (lane == 0) g_Et[t][i][j] = acc;
        } else if (wg < 36) {
            int t = (wg - 27) / 3, j = (wg - 27) % 3;
            for (int c = lane; c < CDIM; c += 32)
                acc = fmaf(dwc_w[c * 9 + t * 3 + 1] * g_W[11][c], w_proj[c * 3 + j], acc);
            acc = warp_sum(acc);
            if (lane == 0) g_Ebt[t][j] = acc;
        } else if (wg < 39) {
            int j = wg - 36;
            for (int c = lane; c < CDIM; c += 32)
                acc = fmaf(g_W[11][c] + dwc_b[c], w_proj[c * 3 + j], acc);
            acc = warp_sum(acc);
            if (lane == 0) g_Const[j] = acc + b_proj[j];
        }
    }
}

// transpose bias2 [N,A] -> [A,N]
__global__ void transB2(const float* __restrict__ bias2) {
    int n0 = blockIdx.x * 16;
    for (int i = threadIdx.x; i < 16 * AGENTS; i += 256) {
        int n = n0 + i / AGENTS, a = i % AGENTS;
        g_b2T[a * NTOK + n] = bias2[n * AGENTS + a];
    }
}

// adaptive avg pool of raw Q per batch
__global__ void poolQ(const float* __restrict__ Q) {
    int b = blockIdx.x;
    int idx = threadIdx.x;
    if (idx < AGENTS * 3) {
        int a = idx / 3, i = idx % 3;
        int s = (a * NTOK) / AGENTS;
        int e = ((a + 1) * NTOK + AGENTS - 1) / AGENTS;
        float acc = 0.f;
        for (int n = s; n < e; n++) acc += Q[(size_t)b * NTOK * 3 + n * 3 + i];
        g_pool[b][a][i] = acc / (float)(e - s);
    }
}

// ---------------------------------------------------------------------------
// stage1: per (b,h) compute cq (store) and pv[a] via stage-1 softmax over N
// ---------------------------------------------------------------------------
__global__ __launch_bounds__(256) void stage1(
    const float* __restrict__ Kg_all, const float* __restrict__ Vg_all,
    const float* __restrict__ bias1) {
    __shared__ float4 sK[NTOK];
    __shared__ float4 sV[NTOK];
    __shared__ float4 sCk[AGENTS];

    const int tid = threadIdx.x;
    const int h = blockIdx.x, b = blockIdx.y;
    const float* Kg = Kg_all + (size_t)b * NTOK * 3;
    const float* Vg = Vg_all + (size_t)b * NTOK * 3;

    for (int n = tid; n < NTOK; n += 256) {
        const float* kp = Kg + n * 3;
        const float* vp = Vg + n * 3;
        sK[n] = make_float4(kp[0], kp[1], kp[2], 0.f);
        sV[n] = make_float4(vp[0], vp[1], vp[2], 0.f);
    }
    if (tid < AGENTS) {
        int a = tid;
        float p0 = g_pool[b][a][0], p1 = g_pool[b][a][1], p2 = g_pool[b][a][2];
        float ck[4], cq[4];
        #pragma unroll
        for (int i = 0; i < 4; i++) {
            ck[i] = g_CkM[h][3][i] + p0 * g_CkM[h][0][i] + p1 * g_CkM[h][1][i] + p2 * g_CkM[h][2][i];
            cq[i] = g_CqM[h][3][i] + p0 * g_CqM[h][0][i] + p1 * g_CqM[h][1][i] + p2 * g_CqM[h][2][i];
        }
        sCk[a] = make_float4(ck[0], ck[1], ck[2], ck[3]);
        g_cq[(b * NHEADS + h) * AGENTS + a] = make_float4(cq[0], cq[1], cq[2], cq[3]);
    }
    __syncthreads();

    const int warp = tid >> 5, lane = tid & 31;
    for (int a = warp; a < AGENTS; a += 8) {
        float4 ck = sCk[a];
        const float* b1 = bias1 + a * NTOK;
        float sc[32];
        float m = -1e30f;
        #pragma unroll
        for (int jj = 0; jj < 32; jj++) {
            int n = jj * 32 + lane;
            float4 k = sK[n];
            float s = fmaf(ck.x, k.x, fmaf(ck.y, k.y, fmaf(ck.z, k.z, ck.w + __ldg(b1 + n))));
            sc[jj] = s;
            m = fmaxf(m, s);
        }
        m = warp_max(m);
        float sum = 0.f, pv0 = 0.f, pv1 = 0.f, pv2 = 0.f;
        #pragma unroll
        for (int jj = 0; jj < 32; jj++) {
            int n = jj * 32 + lane;
            float e = __expf(sc[jj] - m);
            float4 v = sV[n];
            sum += e;
            pv0 = fmaf(e, v.x, pv0);
            pv1 = fmaf(e, v.y, pv1);
            pv2 = fmaf(e, v.z, pv2);
        }
        sum = warp_sum(sum);
        pv0 = warp_sum(pv0);
        pv1 = warp_sum(pv1);
        pv2 = warp_sum(pv2);
        if (lane == 0) {
            float inv = 1.f / sum;
            g_pv[(b * NHEADS + h) * AGENTS + a] = make_float4(pv0 * inv, pv1 * inv, pv2 * inv, 0.f);
        }
    }
}

// ---------------------------------------------------------------------------
// stage2: per (b, 32-token chunk): 16 warps = 16 heads, lane = token.
// Online softmax over 49 agents -> t vector -> G-projected partial, reduce
// over heads, add dwc rank-3 residual + const, write out [B,3,N].
// ---------------------------------------------------------------------------
__global__ __launch_bounds__(512) void stage2(
    const float* __restrict__ Qg_all, const float* __restrict__ Vg_all,
    float* __restrict__ out) {
    __shared__ float4 scq[NHEADS * AGENTS];
    __shared__ float4 spv[NHEADS * AGENTS];
    __shared__ float sred[NHEADS][32][3];

    const int tid = threadIdx.x;
    const int b = blockIdx.y;
    const int h = tid >> 5, lane = tid & 31;
    const int n = blockIdx.x * 32 + lane;

    for (int i = tid; i < NHEADS * AGENTS; i += 512) {
        scq[i] = g_cq[b * NHEADS * AGENTS + i];
        spv[i] = g_pv[b * NHEADS * AGENTS + i];
    }
    __syncthreads();

    const float* qp = Qg_all + (size_t)b * NTOK * 3 + n * 3;
    float q0 = qp[0], q1 = qp[1], q2 = qp[2];

    float m = -1e30f, sum = 0.f, t0 = 0.f, t1 = 0.f, t2 = 0.f;
    const float4* cqh = scq + h * AGENTS;
    const float4* pvh = spv + h * AGENTS;
    #pragma unroll 7
    for (int a = 0; a < AGENTS; a++) {
        float4 cq = cqh[a];
        float s = fmaf(cq.x, q0, fmaf(cq.y, q1, fmaf(cq.z, q2, cq.w + __ldg(&g_b2T[a * NTOK + n]))));
        float nm = fmaxf(m, s);
        float scale = __expf(m - nm);
        float e = __expf(s - nm);
        float4 pv = pvh[a];
        sum = fmaf(sum, scale, e);
        t0 = fmaf(t0, scale, e * pv.x);
        t1 = fmaf(t1, scale, e * pv.y);
        t2 = fmaf(t2, scale, e * pv.z);
        m = nm;
    }
    float inv = 1.f / sum;
    #pragma unroll
    for (int j = 0; j < 3; j++) {
        float p = fmaf(t0, g_G[h][0][j], fmaf(t1, g_G[h][1][j], t2 * g_G[h][2][j]));
        sred[h][lane][j] = p * inv;
    }
    __syncthreads();

    if (tid < 96) {
        int j = tid >> 5, tk = tid & 31;
        int nn = blockIdx.x * 32 + tk;
        float r = g_Const[j];
        #pragma unroll
        for (int hh = 0; hh < NHEADS; hh++) r += sred[hh][tk][j];
        const float* Vb = Vg_all + (size_t)b * NTOK * 3;
        #pragma unroll
        for (int t = 0; t < 3; t++) {
            int mrow = nn - 1 + t;
            if (mrow >= 0 && mrow < NTOK) {
                const float* vp = Vb + mrow * 3;
                r += g_Ebt[t][j];
                r = fmaf(vp[0], g_Et[t][0][j], r);
                r = fmaf(vp[1], g_Et[t][1][j], r);
                r = fmaf(vp[2], g_Et[t][2][j], r);
            }
        }
        out[(size_t)b * 3 * NTOK + j * NTOK + nn] = r;
    }
}

extern "C" void kernel_launch(void* const* d_in, const int* in_sizes, int n_in,
                              void* d_out, int out_size) {
    const float* Q      = (const float*)d_in[0];
    const float* K      = (const float*)d_in[1];
    const float* V      = (const float*)d_in[2];
    const float* w_vel  = (const float*)d_in[3];
    const float* b_vel  = (const float*)d_in[4];
    const float* w_init = (const float*)d_in[5];
    const float* b_init = (const float*)d_in[6];
    const float* wq     = (const float*)d_in[7];
    const float* bq     = (const float*)d_in[8];
    const float* wk     = (const float*)d_in[9];
    const float* bk     = (const float*)d_in[10];
    const float* wv     = (const float*)d_in[11];
    const float* bv     = (const float*)d_in[12];
    const float* ab1    = (const float*)d_in[13];
    const float* ab2    = (const float*)d_in[14];
    const float* dwc_w  = (const float*)d_in[15];
    const float* dwc_b  = (const float*)d_in[16];
    const float* w_proj = (const float*)d_in[17];
    const float* b_proj = (const float*)d_in[18];
    float* out = (float*)d_out;

    prepA<<<dim3(4, 8, 3), 256>>>(w_vel, b_vel, w_init, b_init, wq, wk, wv);
    prepB<<<48, 256>>>(bq, bk, bv);
    prepC<<<21, 256>>>(w_proj, b_proj, dwc_w, dwc_b);
    transB2<<<64, 256>>>(ab2);
    poolQ<<<32, 256>>>(Q);
    stage1<<<dim3(NHEADS, BATCH), 256>>>(K, V, ab1);
    stage2<<<dim3(32, BATCH), 512>>>(Q, V, out);
}

// round 4
// speedup vs baseline: 7.5743x; 1.0158x over previous
#include <cuda_runtime.h>
#include <math.h>

#define BATCH 32
#define NTOK 1024
#define CDIM 1024
#define NHEADS 16
#define HD 64
#define AGENTS 49
#define LOG2E 1.4426950408889634f

// ---------------- precomputed small tensors ----------------
__device__ float g_part[3 * 8 * 4 * CDIM];   // j-split partials of [w|b] @ wq/wk/wv
__device__ float g_W[8][CDIM];               // rows 0-3: Q-path (w0,w1,w2,bias); 4-7: K-path
__device__ float g_G[NHEADS][3][3];          // Wv_h @ w_proj_h
__device__ float g_Et[3][3][3];              // dwc tap x rank-i x out-j
__device__ float g_Ebt[3][3];                // dwc tap bias terms
__device__ float g_Const[3];                 // constant per output channel
__device__ float g_b1s[AGENTS * NTOK];       // bias1 * log2(e)
__device__ float g_pool[BATCH][AGENTS][3];   // pooled raw Q
__device__ float4 g_cq[BATCH * NHEADS * AGENTS];  // stage-2 coeffs (log2-scaled)
__device__ float4 g_pv[BATCH * NHEADS * AGENTS];  // stage-1 softmax·V (normalized)

__device__ __forceinline__ float warp_sum(float v) {
    #pragma unroll
    for (int o = 16; o; o >>= 1) v += __shfl_xor_sync(0xffffffffu, v, o);
    return v;
}

// ---------------------------------------------------------------------------
// prepA: partial fold of [w_vel|b_vel] @ {wq,wk,wv}, j split 16x.
// ---------------------------------------------------------------------------
__global__ __launch_bounds__(256) void prepA(
    const float* __restrict__ w_vel, const float* __restrict__ b_vel,
    const float* __restrict__ w_init, const float* __restrict__ b_init,
    const float* __restrict__ wq, const float* __restrict__ wk,
    const float* __restrict__ wv) {
    int mat = blockIdx.z, jz = blockIdx.y;
    int c = blockIdx.x * 256 + threadIdx.x;
    const float* W = (mat == 0) ? wq : (mat == 1 ? wk : wv);
    const float* A = (mat == 0) ? w_vel : w_init;
    const float* bb = (mat == 0) ? b_vel : b_init;
    float a0 = 0.f, a1 = 0.f, a2 = 0.f, a3 = 0.f;
    int j0 = jz * 64;
    #pragma unroll 8
    for (int j = j0; j < j0 + 64; j++) {
        float w = W[j * CDIM + c];
        a0 = fmaf(__ldg(A + j), w, a0);
        a1 = fmaf(__ldg(A + CDIM + j), w, a1);
        a2 = fmaf(__ldg(A + 2 * CDIM + j), w, a2);
        a3 = fmaf(__ldg(bb + j), w, a3);
    }
    // accumulate two jz into one slot (16 splits -> 8 slots) via disjoint halves
    float* p = g_part + ((mat * 8 + (jz >> 1)) * 4) * CDIM + c;
    if (jz & 1) { // second half writes upper temp region: reuse by atomic-free split
        // write to odd slot offsets: use separate region [half]
        p = g_part + ((mat * 8 + (jz >> 1)) * 4) * CDIM + c; // same slot -> need distinct!
    }
    // NOTE: to keep slots distinct, use jz directly over 16 would need 16 slots.
    // Instead: jz in [0,16) maps to slot jz/2, and we write to row offset (jz&1)*? -> simplest:
    // fall back: store per-jz using 8 slots of 2 rows each is messy; use plain 8-slot layout:
    // (handled below by having jz index 8 slots and 128-j chunks)
    p[0] = a0; p[CDIM] = a1; p[2 * CDIM] = a2; p[3 * CDIM] = a3;
}

// Clean version: 8 j-chunks of 128 with unroll 8 (prepA2 used instead of prepA).
__global__ __launch_bounds__(256) void prepA2(
    const float* __restrict__ w_vel, const float* __restrict__ b_vel,
    const float* __restrict__ w_init, const float* __restrict__ b_init,
    const float* __restrict__ wq, const float* __restrict__ wk,
    const float* __restrict__ wv) {
    int mat = blockIdx.z, jz = blockIdx.y;
    int c = blockIdx.x * 256 + threadIdx.x;
    const float* W = (mat == 0) ? wq : (mat == 1 ? wk : wv);
    const float* A = (mat == 0) ? w_vel : w_init;
    const float* bb = (mat == 0) ? b_vel : b_init;
    float a0 = 0.f, a1 = 0.f, a2 = 0.f, a3 = 0.f;
    int j0 = jz * 128;
    #pragma unroll 8
    for (int j = j0; j < j0 + 128; j++) {
        float w = W[j * CDIM + c];
        a0 = fmaf(__ldg(A + j), w, a0);
        a1 = fmaf(__ldg(A + CDIM + j), w, a1);
        a2 = fmaf(__ldg(A + 2 * CDIM + j), w, a2);
        a3 = fmaf(__ldg(bb + j), w, a3);
    }
    float* p = g_part + ((mat * 8 + jz) * 4) * CDIM + c;
    p[0] = a0; p[CDIM] = a1; p[2 * CDIM] = a2; p[3 * CDIM] = a3;
}

// ---------------------------------------------------------------------------
// prepB: everything else that is input-independent-shaped, one launch.
//  blk 0..31   : reduce Q/K partials -> g_W (+ trailing bias)
//  blk 32..63  : adaptive avg pool of raw Q, batch = blk-32 (warp per agent)
//  blk 64..86  : Et / Ebt / Const / G from V partials (184 warp jobs)
//  blk 87..111 : scale bias1 by log2(e)
// ---------------------------------------------------------------------------
__global__ __launch_bounds__(256) void prepB(
    const float* __restrict__ Q,
    const float* __restrict__ bq, const float* __restrict__ bk,
    const float* __restrict__ bv,
    const float* __restrict__ bias1,
    const float* __restrict__ dwc_w, const float* __restrict__ dwc_b,
    const float* __restrict__ w_proj, const float* __restrict__ b_proj) {
    const int blk = blockIdx.x;
    const int tid = threadIdx.x;
    const int lane = tid & 31, warp = tid >> 5;

    if (blk < 32) {
        int gid = blk * 256 + tid;            // 8192 = 2 mats x 4 rows x 1024
        int mat = gid >> 12;
        int r = (gid >> 10) & 3;
        int c = gid & 1023;
        float s = 0.f;
        #pragma unroll
        for (int jz = 0; jz < 8; jz++)
            s += g_part[((mat * 8 + jz) * 4 + r) * CDIM + c];
        if (r == 3) s += (mat == 0 ? bq : bk)[c];
        g_W[mat * 4 + r][c] = s;
    } else if (blk < 64) {
        int b = blk - 32;
        const float* Qb = Q + (size_t)b * NTOK * 3;
        for (int a = warp; a < AGENTS; a += 8) {
            int s = (a * NTOK) / AGENTS;
            int e = ((a + 1) * NTOK + AGENTS - 1) / AGENTS;
            int cnt = (e - s) * 3;
            float ac0 = 0.f, ac1 = 0.f, ac2 = 0.f;
            #pragma unroll
            for (int k = 0; k < 3; k++) {
                int idx = lane + 32 * k;
                if (idx < cnt) {
                    float v = Qb[s * 3 + idx];
                    int c = idx % 3;
                    ac0 += (c == 0) ? v : 0.f;
                    ac1 += (c == 1) ? v : 0.f;
                    ac2 += (c == 2) ? v : 0.f;
                }
            }
            ac0 = warp_sum(ac0); ac1 = warp_sum(ac1); ac2 = warp_sum(ac2);
            if (lane == 0) {
                float inv = 1.f / (float)(e - s);
                g_pool[b][a][0] = ac0 * inv;
                g_pool[b][a][1] = ac1 * inv;
                g_pool[b][a][2] = ac2 * inv;
            }
        }
    } else if (blk < 87) {
        int wg = (blk - 64) * 8 + warp;
        float acc = 0.f;
        if (wg < 27) {                       // Et[t][i][j]
            int t = wg / 9, rem = wg % 9, i = rem / 3, j = rem % 3;
            for (int c = lane; c < CDIM; c += 32) {
                float wv_i = 0.f;
                #pragma unroll
                for (int jz = 0; jz < 8; jz++)
                    wv_i += g_part[((16 + jz) * 4 + i) * CDIM + c];
                acc = fmaf(dwc_w[c * 9 + t * 3 + 1] * wv_i, w_proj[c * 3 + j], acc);
            }
            acc = warp_sum(acc);
            if (lane == 0) g_Et[t][i][j] = acc;
        } else if (wg < 36) {                // Ebt[t][j]
            int t = (wg - 27) / 3, j = (wg - 27) % 3;
            for (int c = lane; c < CDIM; c += 32) {
                float wvb = bv[c];
                #pragma unroll
                for (int jz = 0; jz < 8; jz++)
                    wvb += g_part[((16 + jz) * 4 + 3) * CDIM + c];
                acc = fmaf(dwc_w[c * 9 + t * 3 + 1] * wvb, w_proj[c * 3 + j], acc);
            }
            acc = warp_sum(acc);
            if (lane == 0) g_Ebt[t][j] = acc;
        } else if (wg < 39) {                // Const[j]
            int j = wg - 36;
            for (int c = lane; c < CDIM; c += 32) {
                float wvb = bv[c] + dwc_b[c];
                #pragma unroll
                for (int jz = 0; jz < 8; jz++)
                    wvb += g_part[((16 + jz) * 4 + 3) * CDIM + c];
                acc = fmaf(wvb, w_proj[c * 3 + j], acc);
            }
            acc = warp_sum(acc);
            if (lane == 0) g_Const[j] = acc + b_proj[j];
        } else if (wg < 183) {               // G[h][i][j]
            int g = wg - 39;
            int h = g / 9, rem = g % 9, i = rem / 3, j = rem % 3;
            #pragma unroll
            for (int k = 0; k < 2; k++) {
                int d = lane + 32 * k;
                int c = h * HD + d;
                float wv_i = 0.f;
                #pragma unroll
                for (int jz = 0; jz < 8; jz++)
                    wv_i += g_part[((16 + jz) * 4 + i) * CDIM + c];
                acc = fmaf(wv_i, w_proj[c * 3 + j], acc);
            }
            acc = warp_sum(acc);
            if (lane == 0) g_G[h][i][j] = acc;
        }
    } else {
        int base = (blk - 87) * 2048;
        #pragma unroll
        for (int k = 0; k < 8; k++) {
            int idx = base + k * 256 + tid;
            if (idx < AGENTS * NTOK) g_b1s[idx] = bias1[idx] * LOG2E;
        }
    }
}

// ---------------------------------------------------------------------------
// stage1: per (b,h). Prologue computes per-head 4x4 coeff matrices inline,
// then single-pass (no-max) softmax-weighted V reduction per agent row.
// ---------------------------------------------------------------------------
__global__ __launch_bounds__(256) void stage1(
    const float* __restrict__ Kg_all, const float* __restrict__ Vg_all) {
    __shared__ float4 sK[NTOK];
    __shared__ float4 sV[NTOK];
    __shared__ float sW[8][HD];
    __shared__ float sCkM[4][4], sCqM[4][4];
    __shared__ float4 sCk[AGENTS];

    const int tid = threadIdx.x;
    const int h = blockIdx.x, b = blockIdx.y;
    const float* Kg = Kg_all + (size_t)b * NTOK * 3;
    const float* Vg = Vg_all + (size_t)b * NTOK * 3;

    for (int idx = tid; idx < 8 * HD; idx += 256) {
        int r = idx >> 6, d = idx & 63;
        sW[r][d] = g_W[r][h * HD + d];
    }
    for (int n = tid; n < NTOK; n += 256) {
        const float* kp = Kg + n * 3;
        const float* vp = Vg + n * 3;
        sK[n] = make_float4(kp[0], kp[1], kp[2], 0.f);
        sV[n] = make_float4(vp[0], vp[1], vp[2], 0.f);
    }
    __syncthreads();

    if (tid < 32) {
        int q = tid & 15;
        int j = q >> 2, i = q & 3;
        const float* rq = sW[j];
        const float* rx = (tid < 16) ? sW[4 + i] : sW[i];
        float s = 0.f;
        #pragma unroll 8
        for (int d = 0; d < HD; d++) s = fmaf(rq[d], rx[d], s);
        if (tid < 16) sCkM[j][i] = s; else sCqM[j][i] = s;
    }
    __syncthreads();

    if (tid < AGENTS) {
        int a = tid;
        float p0 = g_pool[b][a][0], p1 = g_pool[b][a][1], p2 = g_pool[b][a][2];
        float ck[4], cq[4];
        #pragma unroll
        for (int i = 0; i < 4; i++) {
            ck[i] = LOG2E * (sCkM[3][i] + p0 * sCkM[0][i] + p1 * sCkM[1][i] + p2 * sCkM[2][i]);
            cq[i] = LOG2E * (sCqM[3][i] + p0 * sCqM[0][i] + p1 * sCqM[1][i] + p2 * sCqM[2][i]);
        }
        sCk[a] = make_float4(ck[0], ck[1], ck[2], ck[3]);
        g_cq[(b * NHEADS + h) * AGENTS + a] = make_float4(cq[0], cq[1], cq[2], cq[3]);
    }
    __syncthreads();

    const int warp = tid >> 5, lane = tid & 31;
    for (int a = warp; a < AGENTS; a += 8) {
        float4 ck = sCk[a];
        const float* b1 = g_b1s + a * NTOK;
        float sum = 0.f, pv0 = 0.f, pv1 = 0.f, pv2 = 0.f;
        #pragma unroll
        for (int jj = 0; jj < 32; jj++) {
            int n = jj * 32 + lane;
            float4 k = sK[n];
            float s = fmaf(ck.x, k.x, fmaf(ck.y, k.y, fmaf(ck.z, k.z, ck.w + __ldg(b1 + n))));
            float e = exp2f(s);
            float4 v = sV[n];
            sum += e;
            pv0 = fmaf(e, v.x, pv0);
            pv1 = fmaf(e, v.y, pv1);
            pv2 = fmaf(e, v.z, pv2);
        }
        sum = warp_sum(sum);
        pv0 = warp_sum(pv0);
        pv1 = warp_sum(pv1);
        pv2 = warp_sum(pv2);
        if (lane == 0) {
            float inv = 1.f / sum;
            g_pv[(b * NHEADS + h) * AGENTS + a] =
                make_float4(pv0 * inv, pv1 * inv, pv2 * inv, 0.f);
        }
    }
}

// ---------------------------------------------------------------------------
// stage2: per (b, 32-token chunk): warp = head, lane = token. Single-pass
// (no-max) softmax over 49 agents, G-projected partial, reduce over heads,
// add dwc rank-3 residual + const, write out [B,3,N].
// ---------------------------------------------------------------------------
__global__ __launch_bounds__(512) void stage2(
    const float* __restrict__ Qg_all, const float* __restrict__ Vg_all,
    const float* __restrict__ bias2, float* __restrict__ out) {
    __shared__ float4 scq[NHEADS * AGENTS];
    __shared__ float4 spv[NHEADS * AGENTS];
    __shared__ float sb2[AGENTS * 32];
    __shared__ float sred[NHEADS][32][3];

    const int tid = threadIdx.x;
    const int b = blockIdx.y;
    const int h = tid >> 5, lane = tid & 31;
    const int n0 = blockIdx.x * 32;
    const int n = n0 + lane;

    for (int i = tid; i < NHEADS * AGENTS; i += 512) {
        scq[i] = g_cq[b * NHEADS * AGENTS + i];
        spv[i] = g_pv[b * NHEADS * AGENTS + i];
    }
    for (int i = tid; i < AGENTS * 32; i += 512) {
        int nn = i / AGENTS, a = i % AGENTS;
        sb2[a * 32 + nn] = bias2[(size_t)(n0 + nn) * AGENTS + a] * LOG2E;
    }
    __syncthreads();

    const float* qp = Qg_all + (size_t)b * NTOK * 3 + n * 3;
    float q0 = qp[0], q1 = qp[1], q2 = qp[2];

    float sum = 0.f, t0 = 0.f, t1 = 0.f, t2 = 0.f;
    const float4* cqh = scq + h * AGENTS;
    const float4* pvh = spv + h * AGENTS;
    #pragma unroll 7
    for (int a = 0; a < AGENTS; a++) {
        float4 cq = cqh[a];
        float s = fmaf(cq.x, q0, fmaf(cq.y, q1, fmaf(cq.z, q2, cq.w + sb2[a * 32 + lane])));
        float e = exp2f(s);
        float4 pv = pvh[a];
        sum += e;
        t0 = fmaf(e, pv.x, t0);
        t1 = fmaf(e, pv.y, t1);
        t2 = fmaf(e, pv.z, t2);
    }
    float inv = 1.f / sum;
    #pragma unroll
    for (int j = 0; j < 3; j++) {
        float p = fmaf(t0, g_G[h][0][j], fmaf(t1, g_G[h][1][j], t2 * g_G[h][2][j]));
        sred[h][lane][j] = p * inv;
    }
    __syncthreads();

    if (tid < 96) {
        int j = tid >> 5, tk = tid & 31;
        int nn = n0 + tk;
        float r = g_Const[j];
        #pragma unroll
        for (int hh = 0; hh < NHEADS; hh++) r += sred[hh][tk][j];
        const float* Vb = Vg_all + (size_t)b * NTOK * 3;
        #pragma unroll
        for (int t = 0; t < 3; t++) {
            int mrow = nn - 1 + t;
            if (mrow >= 0 && mrow < NTOK) {
                const float* vp = Vb + mrow * 3;
                r += g_Ebt[t][j];
                r = fmaf(vp[0], g_Et[t][0][j], r);
                r = fmaf(vp[1], g_Et[t][1][j], r);
                r = fmaf(vp[2], g_Et[t][2][j], r);
            }
        }
        out[(size_t)b * 3 * NTOK + j * NTOK + nn] = r;
    }
}

extern "C" void kernel_launch(void* const* d_in, const int* in_sizes, int n_in,
                              void* d_out, int out_size) {
    const float* Q      = (const float*)d_in[0];
    const float* K      = (const float*)d_in[1];
    const float* V      = (const float*)d_in[2];
    const float* w_vel  = (const float*)d_in[3];
    const float* b_vel  = (const float*)d_in[4];
    const float* w_init = (const float*)d_in[5];
    const float* b_init = (const float*)d_in[6];
    const float* wq     = (const float*)d_in[7];
    const float* bq     = (const float*)d_in[8];
    const float* wk     = (const float*)d_in[9];
    const float* bk     = (const float*)d_in[10];
    const float* wv     = (const float*)d_in[11];
    const float* bv     = (const float*)d_in[12];
    const float* ab1    = (const float*)d_in[13];
    const float* ab2    = (const float*)d_in[14];
    const float* dwc_w  = (const float*)d_in[15];
    const float* dwc_b  = (const float*)d_in[16];
    const float* w_proj = (const float*)d_in[17];
    const float* b_proj = (const float*)d_in[18];
    float* out = (float*)d_out;

    prepA2<<<dim3(4, 8, 3), 256>>>(w_vel, b_vel, w_init, b_init, wq, wk, wv);
    prepB<<<112, 256>>>(Q, bq, bk, bv, ab1, dwc_w, dwc_b, w_proj, b_proj);
    stage1<<<dim3(NHEADS, BATCH), 256>>>(K, V);
    stage2<<<dim3(32, BATCH), 512>>>(Q, V, ab2, out);
}

// round 6
// speedup vs baseline: 8.7869x; 1.1601x over previous
#include <cuda_runtime.h>
#include <math.h>

#define BATCH 32
#define NTOK 1024
#define CDIM 1024
#define NHEADS 16
#define HD 64
#define AGENTS 49
#define LOG2E 1.4426950408889634f

// ---------------- precomputed small tensors ----------------
__device__ float g_part[3 * 16 * 4 * CDIM];  // j-split partials of [w|b] @ wq/wk/wv
__device__ float g_W[8][CDIM];               // rows 0-3: Q-path (w0,w1,w2,bias); 4-7: K-path
__device__ float g_G[NHEADS][3][3];          // Wv_h @ w_proj_h
__device__ float g_Et[3][3][3];              // dwc tap x rank-i x out-j
__device__ float g_Ebt[3][3];                // dwc tap bias terms
__device__ float g_Const[3];                 // constant per output channel
__device__ float g_b1s[AGENTS * NTOK];       // bias1 * log2(e)
__device__ float g_pool[BATCH][AGENTS][3];   // pooled raw Q
__device__ float4 g_cq[BATCH * NHEADS * AGENTS];  // stage-2 coeffs (log2-scaled)
__device__ float4 g_gv[BATCH * NHEADS * AGENTS];  // normalized (pv·G_h)/sum

__device__ __forceinline__ float warp_sum(float v) {
    #pragma unroll
    for (int o = 16; o; o >>= 1) v += __shfl_xor_sync(0xffffffffu, v, o);
    return v;
}
__device__ __forceinline__ float ex2(float x) {
    float r;
    asm("ex2.approx.ftz.f32 %0, %1;" : "=f"(r) : "f"(x));
    return r;
}

// ---------------------------------------------------------------------------
// prepA: partial fold of [w_vel|b_vel] @ {wq,wk,wv}, j split 16x (64 each).
// ---------------------------------------------------------------------------
__global__ __launch_bounds__(256) void prepA(
    const float* __restrict__ w_vel, const float* __restrict__ b_vel,
    const float* __restrict__ w_init, const float* __restrict__ b_init,
    const float* __restrict__ wq, const float* __restrict__ wk,
    const float* __restrict__ wv) {
    int mat = blockIdx.z, jz = blockIdx.y;
    int c = blockIdx.x * 256 + threadIdx.x;
    const float* W = (mat == 0) ? wq : (mat == 1 ? wk : wv);
    const float* A = (mat == 0) ? w_vel : w_init;
    const float* bb = (mat == 0) ? b_vel : b_init;
    float a0 = 0.f, a1 = 0.f, a2 = 0.f, a3 = 0.f;
    int j0 = jz * 64;
    #pragma unroll 8
    for (int j = j0; j < j0 + 64; j++) {
        float w = W[j * CDIM + c];
        a0 = fmaf(__ldg(A + j), w, a0);
        a1 = fmaf(__ldg(A + CDIM + j), w, a1);
        a2 = fmaf(__ldg(A + 2 * CDIM + j), w, a2);
        a3 = fmaf(__ldg(bb + j), w, a3);
    }
    float* p = g_part + ((mat * 16 + jz) * 4) * CDIM + c;
    p[0] = a0; p[CDIM] = a1; p[2 * CDIM] = a2; p[3 * CDIM] = a3;
}

// ---------------------------------------------------------------------------
// prepB:
//  blk 0..31   : reduce Q/K partials -> g_W (+ trailing bias)
//  blk 32..63  : adaptive avg pool of raw Q (batch = blk-32)
//  blk 64..86  : Et / Ebt / Const / G from V partials (184 warp jobs)
//  blk 87..111 : scale bias1 by log2(e)
// ---------------------------------------------------------------------------
__global__ __launch_bounds__(256) void prepB(
    const float* __restrict__ Q,
    const float* __restrict__ bq, const float* __restrict__ bk,
    const float* __restrict__ bv,
    const float* __restrict__ bias1,
    const float* __restrict__ dwc_w, const float* __restrict__ dwc_b,
    const float* __restrict__ w_proj, const float* __restrict__ b_proj) {
    const int blk = blockIdx.x;
    const int tid = threadIdx.x;
    const int lane = tid & 31, warp = tid >> 5;

    if (blk < 32) {
        int gid = blk * 256 + tid;            // 8192 = 2 mats x 4 rows x 1024
        int mat = gid >> 12;
        int r = (gid >> 10) & 3;
        int c = gid & 1023;
        float s = 0.f;
        #pragma unroll
        for (int jz = 0; jz < 16; jz++)
            s += g_part[((mat * 16 + jz) * 4 + r) * CDIM + c];
        if (r == 3) s += (mat == 0 ? bq : bk)[c];
        g_W[mat * 4 + r][c] = s;
    } else if (blk < 64) {
        int b = blk - 32;
        const float* Qb = Q + (size_t)b * NTOK * 3;
        for (int a = warp; a < AGENTS; a += 8) {
            int s = (a * NTOK) / AGENTS;
            int e = ((a + 1) * NTOK + AGENTS - 1) / AGENTS;
            int cnt = (e - s) * 3;
            float ac0 = 0.f, ac1 = 0.f, ac2 = 0.f;
            #pragma unroll
            for (int k = 0; k < 3; k++) {
                int idx = lane + 32 * k;
                if (idx < cnt) {
                    float v = Qb[s * 3 + idx];
                    int c = idx % 3;
                    ac0 += (c == 0) ? v : 0.f;
                    ac1 += (c == 1) ? v : 0.f;
                    ac2 += (c == 2) ? v : 0.f;
                }
            }
            ac0 = warp_sum(ac0); ac1 = warp_sum(ac1); ac2 = warp_sum(ac2);
            if (lane == 0) {
                float inv = 1.f / (float)(e - s);
                g_pool[b][a][0] = ac0 * inv;
                g_pool[b][a][1] = ac1 * inv;
                g_pool[b][a][2] = ac2 * inv;
            }
        }
    } else if (blk < 87) {
        int wg = (blk - 64) * 8 + warp;
        float acc = 0.f;
        if (wg < 27) {                       // Et[t][i][j]
            int t = wg / 9, rem = wg % 9, i = rem / 3, j = rem % 3;
            for (int c = lane; c < CDIM; c += 32) {
                float wv_i = 0.f;
                #pragma unroll
                for (int jz = 0; jz < 16; jz++)
                    wv_i += g_part[((32 + jz) * 4 + i) * CDIM + c];
                acc = fmaf(dwc_w[c * 9 + t * 3 + 1] * wv_i, w_proj[c * 3 + j], acc);
            }
            acc = warp_sum(acc);
            if (lane == 0) g_Et[t][i][j] = acc;
        } else if (wg < 36) {                // Ebt[t][j]
            int t = (wg - 27) / 3, j = (wg - 27) % 3;
            for (int c = lane; c < CDIM; c += 32) {
                float wvb = bv[c];
                #pragma unroll
                for (int jz = 0; jz < 16; jz++)
                    wvb += g_part[((32 + jz) * 4 + 3) * CDIM + c];
                acc = fmaf(dwc_w[c * 9 + t * 3 + 1] * wvb, w_proj[c * 3 + j], acc);
            }
            acc = warp_sum(acc);
            if (lane == 0) g_Ebt[t][j] = acc;
        } else if (wg < 39) {                // Const[j]
            int j = wg - 36;
            for (int c = lane; c < CDIM; c += 32) {
                float wvb = bv[c] + dwc_b[c];
                #pragma unroll
                for (int jz = 0; jz < 16; jz++)
                    wvb += g_part[((32 + jz) * 4 + 3) * CDIM + c];
                acc = fmaf(wvb, w_proj[c * 3 + j], acc);
            }
            acc = warp_sum(acc);
            if (lane == 0) g_Const[j] = acc + b_proj[j];
        } else if (wg < 183) {               // G[h][i][j]
            int g = wg - 39;
            int h = g / 9, rem = g % 9, i = rem / 3, j = rem % 3;
            #pragma unroll
            for (int k = 0; k < 2; k++) {
                int d = lane + 32 * k;
                int c = h * HD + d;
                float wv_i = 0.f;
                #pragma unroll
                for (int jz = 0; jz < 16; jz++)
                    wv_i += g_part[((32 + jz) * 4 + i) * CDIM + c];
                acc = fmaf(wv_i, w_proj[c * 3 + j], acc);
            }
            acc = warp_sum(acc);
            if (lane == 0) g_G[h][i][j] = acc;
        }
    } else {
        int base = (blk - 87) * 2048;
        #pragma unroll
        for (int k = 0; k < 8; k++) {
            int idx = base + k * 256 + tid;
            if (idx < AGENTS * NTOK) g_b1s[idx] = bias1[idx] * LOG2E;
        }
    }
}

// ---------------------------------------------------------------------------
// stage1: per (b,h). 7 warps x 7 agents each; one K/V load serves 7 scores.
// Stores cq (log2-scaled) and gv = (pv·G_h)/sum per agent.
// ---------------------------------------------------------------------------
__global__ __launch_bounds__(256) void stage1(
    const float* __restrict__ Kg_all, const float* __restrict__ Vg_all) {
    __shared__ float4 sK[NTOK];
    __shared__ float4 sV[NTOK];
    __shared__ float sW[8][HD];
    __shared__ float sCkM[4][4], sCqM[4][4];
    __shared__ float4 sCk[AGENTS];
    __shared__ float sG[9];

    const int tid = threadIdx.x;
    const int h = blockIdx.x, b = blockIdx.y;
    const float* Kg = Kg_all + (size_t)b * NTOK * 3;
    const float* Vg = Vg_all + (size_t)b * NTOK * 3;

    for (int idx = tid; idx < 8 * HD; idx += 256) {
        int r = idx >> 6, d = idx & 63;
        sW[r][d] = g_W[r][h * HD + d];
    }
    for (int n = tid; n < NTOK; n += 256) {
        const float* kp = Kg + n * 3;
        const float* vp = Vg + n * 3;
        sK[n] = make_float4(kp[0], kp[1], kp[2], 0.f);
        sV[n] = make_float4(vp[0], vp[1], vp[2], 0.f);
    }
    if (tid >= 128 && tid < 137) {
        int q = tid - 128;
        sG[q] = g_G[h][q / 3][q % 3];
    }
    __syncthreads();

    if (tid < 32) {
        int q = tid & 15;
        int j = q >> 2, i = q & 3;
        const float* rq = sW[j];
        const float* rx = (tid < 16) ? sW[4 + i] : sW[i];
        float s = 0.f;
        #pragma unroll 8
        for (int d = 0; d < HD; d++) s = fmaf(rq[d], rx[d], s);
        if (tid < 16) sCkM[j][i] = s; else sCqM[j][i] = s;
    }
    __syncthreads();

    if (tid < AGENTS) {
        int a = tid;
        float p0 = g_pool[b][a][0], p1 = g_pool[b][a][1], p2 = g_pool[b][a][2];
        float ck[4], cq[4];
        #pragma unroll
        for (int i = 0; i < 4; i++) {
            ck[i] = LOG2E * (sCkM[3][i] + p0 * sCkM[0][i] + p1 * sCkM[1][i] + p2 * sCkM[2][i]);
            cq[i] = LOG2E * (sCqM[3][i] + p0 * sCqM[0][i] + p1 * sCqM[1][i] + p2 * sCqM[2][i]);
        }
        sCk[a] = make_float4(ck[0], ck[1], ck[2], ck[3]);
        g_cq[(b * NHEADS + h) * AGENTS + a] = make_float4(cq[0], cq[1], cq[2], cq[3]);
    }
    __syncthreads();

    const int warp = tid >> 5, lane = tid & 31;
    if (warp < 7) {
        const int a0 = warp * 7;
        float4 ck[7];
        float sum[7], p0[7], p1[7], p2[7];
        #pragma unroll
        for (int i = 0; i < 7; i++) {
            ck[i] = sCk[a0 + i];
            sum[i] = 0.f; p0[i] = 0.f; p1[i] = 0.f; p2[i] = 0.f;
        }
        #pragma unroll 4
        for (int jj = 0; jj < 32; jj++) {
            int n = jj * 32 + lane;
            float4 k = sK[n];
            float4 v = sV[n];
            #pragma unroll
            for (int i = 0; i < 7; i++) {
                float b1v = __ldg(g_b1s + (a0 + i) * NTOK + n);
                float s = fmaf(ck[i].x, k.x, fmaf(ck[i].y, k.y, fmaf(ck[i].z, k.z, ck[i].w + b1v)));
                float e = ex2(s);
                sum[i] += e;
                p0[i] = fmaf(e, v.x, p0[i]);
                p1[i] = fmaf(e, v.y, p1[i]);
                p2[i] = fmaf(e, v.z, p2[i]);
            }
        }
        #pragma unroll
        for (int i = 0; i < 7; i++) {
            float su = warp_sum(sum[i]);
            float q0 = warp_sum(p0[i]);
            float q1 = warp_sum(p1[i]);
            float q2 = warp_sum(p2[i]);
            if (lane == 0) {
                float inv = 1.f / su;
                float gv0 = (q0 * sG[0] + q1 * sG[3] + q2 * sG[6]) * inv;
                float gv1 = (q0 * sG[1] + q1 * sG[4] + q2 * sG[7]) * inv;
                float gv2 = (q0 * sG[2] + q1 * sG[5] + q2 * sG[8]) * inv;
                g_gv[(b * NHEADS + h) * AGENTS + a0 + i] = make_float4(gv0, gv1, gv2, 0.f);
            }
        }
    }
}

// ---------------------------------------------------------------------------
// stage2: CTA = (b, 64-token tile). 16 warps = 16 heads; lane = token; 2
// token groups per warp with cq/gv loaded once per agent. Softmax over 49
// agents (no-max), accumulate G-folded gv, reduce heads, add dwc, write out.
// ---------------------------------------------------------------------------
__global__ __launch_bounds__(512) void stage2(
    const float* __restrict__ Qg_all, const float* __restrict__ Vg_all,
    const float* __restrict__ bias2, float* __restrict__ out) {
    __shared__ float4 scq[NHEADS * AGENTS];
    __shared__ float4 sgv[NHEADS * AGENTS];
    __shared__ float sb2[AGENTS * 65];       // padded: bank = (a + nn) % 32
    __shared__ float sred[NHEADS][32][3];

    const int tid = threadIdx.x;
    const int b = blockIdx.y;
    const int h = tid >> 5, lane = tid & 31;
    const int t0 = blockIdx.x * 64;

    for (int i = tid; i < NHEADS * AGENTS; i += 512) {
        scq[i] = g_cq[b * NHEADS * AGENTS + i];
        sgv[i] = g_gv[b * NHEADS * AGENTS + i];
    }
    for (int i = tid; i < 64 * AGENTS; i += 512) {
        int nn = i / AGENTS, a = i % AGENTS;
        sb2[a * 65 + nn] = bias2[(size_t)(t0 + nn) * AGENTS + a] * LOG2E;
    }
    __syncthreads();

    float q0[2], q1[2], q2[2];
    #pragma unroll
    for (int g = 0; g < 2; g++) {
        const float* qp = Qg_all + (size_t)b * NTOK * 3 + (t0 + g * 32 + lane) * 3;
        q0[g] = qp[0]; q1[g] = qp[1]; q2[g] = qp[2];
    }

    float su[2] = {0.f, 0.f};
    float u0[2] = {0.f, 0.f}, u1[2] = {0.f, 0.f}, u2[2] = {0.f, 0.f};
    const float4* cqh = scq + h * AGENTS;
    const float4* gvh = sgv + h * AGENTS;
    #pragma unroll 7
    for (int a = 0; a < AGENTS; a++) {
        float4 cq = cqh[a];
        float4 gv = gvh[a];
        #pragma unroll
        for (int g = 0; g < 2; g++) {
            float b2v = sb2[a * 65 + (g << 5) + lane];
            float s = fmaf(cq.x, q0[g], fmaf(cq.y, q1[g], fmaf(cq.z, q2[g], cq.w + b2v)));
            float e = ex2(s);
            su[g] += e;
            u0[g] = fmaf(e, gv.x, u0[g]);
            u1[g] = fmaf(e, gv.y, u1[g]);
            u2[g] = fmaf(e, gv.z, u2[g]);
        }
    }

    #pragma unroll
    for (int g = 0; g < 2; g++) {
        float inv = 1.f / su[g];
        sred[h][lane][0] = u0[g] * inv;
        sred[h][lane][1] = u1[g] * inv;
        sred[h][lane][2] = u2[g] * inv;
        __syncthreads();
        if (tid < 96) {
            int j = tid >> 5, tk = tid & 31;
            int nn = t0 + g * 32 + tk;
            float r = g_Const[j];
            #pragma unroll
            for (int hh = 0; hh < NHEADS; hh++) r += sred[hh][tk][j];
            const float* Vb = Vg_all + (size_t)b * NTOK * 3;
            #pragma unroll
            for (int t = 0; t < 3; t++) {
                int mrow = nn - 1 + t;
                if (mrow >= 0 && mrow < NTOK) {
                    const float* vp = Vb + mrow * 3;
                    r += g_Ebt[t][j];
                    r = fmaf(vp[0], g_Et[t][0][j], r);
                    r = fmaf(vp[1], g_Et[t][1][j], r);
                    r = fmaf(vp[2], g_Et[t][2][j], r);
                }
            }
            out[(size_t)b * 3 * NTOK + j * NTOK + nn] = r;
        }
        __syncthreads();
    }
}

extern "C" void kernel_launch(void* const* d_in, const int* in_sizes, int n_in,
                              void* d_out, int out_size) {
    const float* Q      = (const float*)d_in[0];
    const float* K      = (const float*)d_in[1];
    const float* V      = (const float*)d_in[2];
    const float* w_vel  = (const float*)d_in[3];
    const float* b_vel  = (const float*)d_in[4];
    const float* w_init = (const float*)d_in[5];
    const float* b_init = (const float*)d_in[6];
    const float* wq     = (const float*)d_in[7];
    const float* bq     = (const float*)d_in[8];
    const float* wk     = (const float*)d_in[9];
    const float* bk     = (const float*)d_in[10];
    const float* wv     = (const float*)d_in[11];
    const float* bv     = (const float*)d_in[12];
    const float* ab1    = (const float*)d_in[13];
    const float* ab2    = (const float*)d_in[14];
    const float* dwc_w  = (const float*)d_in[15];
    const float* dwc_b  = (const float*)d_in[16];
    const float* w_proj = (const float*)d_in[17];
    const float* b_proj = (const float*)d_in[18];
    float* out = (float*)d_out;

    prepA<<<dim3(4, 16, 3), 256>>>(w_vel, b_vel, w_init, b_init, wq, wk, wv);
    prepB<<<112, 256>>>(Q, bq, bk, bv, ab1, dwc_w, dwc_b, w_proj, b_proj);
    stage1<<<dim3(NHEADS, BATCH), 256>>>(K, V);
    stage2<<<dim3(16, BATCH), 512>>>(Q, V, ab2, out);
}